// round 1
// baseline (speedup 1.0000x reference)
#include <cuda_runtime.h>
#include <cstddef>

// Problem constants (fixed shapes per reference: B=4, C=16, H=W=512)
#define BB 4
#define CC 16
#define HH 512
#define WW 512
#define NN (HH * WW)          // 262144 nodes per batch image
#define LOGW 9                // W = 512 = 1<<9

// ---------------------------------------------------------------------------
// Kernel 1: (B, C, H, W) -> node_features (B*H*W, C)
// thread = one pixel p of one batch b; 16 coalesced strided loads (one per
// channel plane), 4 coalesced float4 stores (one contiguous 64B node row).
// ---------------------------------------------------------------------------
__global__ void transpose_kernel(const float* __restrict__ in,
                                 float* __restrict__ out) {
    int p = blockIdx.x * blockDim.x + threadIdx.x;   // pixel index 0..N-1
    int b = blockIdx.y;
    if (p >= NN) return;

    const float* src = in + (size_t)b * CC * NN + p;
    float v[CC];
#pragma unroll
    for (int c = 0; c < CC; c++) v[c] = src[(size_t)c * NN];

    float4* o = (float4*)(out + ((size_t)b * NN + p) * CC);
#pragma unroll
    for (int k = 0; k < 4; k++)
        o[k] = make_float4(v[4 * k], v[4 * k + 1], v[4 * k + 2], v[4 * k + 3]);
}

// ---------------------------------------------------------------------------
// Kernel 2: edge_index (int32) -> float copy into output
// ---------------------------------------------------------------------------
__global__ void eidx_kernel(const int* __restrict__ ei,
                            float* __restrict__ out, int n) {
    int i = blockIdx.x * blockDim.x + threadIdx.x;
    if (i < n) out[i] = (float)ei[i];
}

// ---------------------------------------------------------------------------
// Kernel 3: per-edge attr.
//   spatial_dist: 8-connectivity => 1.0 (axis) or sqrt(2) (diagonal). No sqrt.
//   feature_diff: (1/(B*C)) * sum_{b,c} |nf[b,src,c] - nf[b,dst,c]|
// Gathers 64B rows per (batch, node) — hot in L2 since kernel 1 just wrote it.
// ---------------------------------------------------------------------------
__global__ void edge_kernel(const int* __restrict__ ei,
                            const float* __restrict__ nf,
                            float* __restrict__ attr, int E) {
    int e = blockIdx.x * blockDim.x + threadIdx.x;
    if (e >= E) return;

    int s = ei[e];
    int d = ei[E + e];

    int sh = s >> LOGW, sw = s & (WW - 1);
    int dh = d >> LOGW, dw = d & (WW - 1);
    int ddh = sh - dh, ddw = sw - dw;
    float dist = ((ddh * ddh + ddw * ddw) == 2) ? 1.41421356237309515f : 1.0f;

    float acc = 0.0f;
#pragma unroll
    for (int b = 0; b < BB; b++) {
        const float4* ps = (const float4*)(nf + ((size_t)b * NN + s) * CC);
        const float4* pd = (const float4*)(nf + ((size_t)b * NN + d) * CC);
#pragma unroll
        for (int k = 0; k < 4; k++) {
            float4 a = ps[k];
            float4 c = pd[k];
            acc += fabsf(a.x - c.x) + fabsf(a.y - c.y) +
                   fabsf(a.z - c.z) + fabsf(a.w - c.w);
        }
    }

    ((float2*)attr)[e] = make_float2(dist, acc * (1.0f / (BB * CC)));
}

// ---------------------------------------------------------------------------
// Launch: output layout = node_features | edge_index(as float) | edge_attr
// ---------------------------------------------------------------------------
extern "C" void kernel_launch(void* const* d_in, const int* in_sizes, int n_in,
                              void* d_out, int out_size) {
    const float* grid = (const float*)d_in[0];
    const int*   ei   = (const int*)d_in[1];

    int E2 = in_sizes[1];   // 2 * E
    int E  = E2 / 2;

    float* out  = (float*)d_out;
    float* nf   = out;                                  // B*N*C floats
    float* eio  = out + (size_t)BB * NN * CC;           // E2 floats
    float* attr = eio + E2;                             // E2 floats

    // 1) transpose to node features
    transpose_kernel<<<dim3(NN / 256, BB), 256>>>(grid, nf);

    // 2) edge_index -> float
    eidx_kernel<<<(E2 + 255) / 256, 256>>>(ei, eio, E2);

    // 3) edge attributes (reads nf written above; same stream => ordered)
    edge_kernel<<<(E + 255) / 256, 256>>>(ei, nf, attr, E);
}

// round 3
// speedup vs baseline: 1.1659x; 1.1659x over previous
#include <cuda_runtime.h>
#include <cstddef>

// Fixed shapes: B=4, C=16, H=W=512
#define BB 4
#define CC 16
#define HH 512
#define WW 512
#define NN (HH * WW)            // 262144 pixels per image
#define NPLANES (BB * CC)       // 64 planes, contiguous in NCHW
#define E_CNT 2091012           // total directed edges (analytic, verified)

// Tile for edge kernel
#define TX 32
#define TY 16
#define SROWS (TY + 1)          // bottom halo only
#define SCOLS (TX + 2)          // left+right halo
#define SELEMS (SROWS * SCOLS)  // 17*34 = 578

// ---------------------------------------------------------------------------
// Analytic edge-start offset of node (h,w) in the reference's edge ordering
// (node-major, then _OFFSETS order with invalid masked out).
//   count(h,w) = vh*vw - 1,  vh,vw in {2,3}
//   row totals: border 5W-4 = 2556, interior 8W-6 = 4090
// ---------------------------------------------------------------------------
__device__ __forceinline__ int edge_start(int h, int w) {
    int R  = (h == 0) ? 0 : 2556 + (h - 1) * 4090;
    int vh = (h == 0 || h == HH - 1) ? 2 : 3;
    int Sv = (w == 0) ? 0 : 3 * w - 1;
    return R + vh * Sv - w;
}

// ---------------------------------------------------------------------------
// Kernel 1: (B, C, H, W) -> node_features (B*H*W, C).
// Thread handles 4 consecutive pixels: 16 float4 loads (512B/warp/instr),
// 16 float4 stores into a 256B contiguous run per thread.
// ---------------------------------------------------------------------------
__global__ void __launch_bounds__(256) transpose_kernel(const float* __restrict__ in,
                                                        float* __restrict__ out) {
    int t  = blockIdx.x * 256 + threadIdx.x;
    int p4 = t * 4;                       // first of 4 pixels
    int b  = blockIdx.y;

    const float* src = in + (size_t)b * CC * NN + p4;
    float4 v[CC];
#pragma unroll
    for (int c = 0; c < CC; c++)
        v[c] = *(const float4*)(src + (size_t)c * NN);

    float* o = out + ((size_t)b * NN + p4) * CC;
#pragma unroll
    for (int j = 0; j < 4; j++) {         // pixel within the 4-pack
#pragma unroll
        for (int k = 0; k < 4; k++) {     // channel quad
            float4 w = make_float4((&v[4 * k + 0].x)[j],
                                   (&v[4 * k + 1].x)[j],
                                   (&v[4 * k + 2].x)[j],
                                   (&v[4 * k + 3].x)[j]);
            *(float4*)(o + j * CC + k * 4) = w;
        }
    }
}

// ---------------------------------------------------------------------------
// Kernel 2 (fused): edge_index floats + edge_attr, all analytic, no gathers.
// Block = 32x16 tile. Loop over 64 planes with double-buffered smem
// (tile + right/bottom/left halo). Each thread accumulates |diff| sums to
// its E, SW, S, SE neighbors; at the end writes BOTH directed edges of each
// undirected pair (positions closed-form), plus the src/dst index floats.
// ---------------------------------------------------------------------------
__global__ void __launch_bounds__(TX * TY) edge_fused_kernel(const float* __restrict__ grid,
                                                             float* __restrict__ eio,
                                                             float2* __restrict__ attr) {
    __shared__ float sb[2][SELEMS];

    int tx = threadIdx.x, ty = threadIdx.y;
    int tid = ty * TX + tx;
    int x0 = blockIdx.x * TX, y0 = blockIdx.y * TY;

    // plane-independent gmem offsets for the (up to) 2 smem slots this thread fills
    int r0 = tid / SCOLS, c0 = tid % SCOLS;
    int gy0 = min(y0 + r0, HH - 1);
    int gx0 = min(max(x0 - 1 + c0, 0), WW - 1);
    int off0 = gy0 * WW + gx0;

    int t1 = tid + TX * TY;
    bool has1 = t1 < SELEMS;
    int off1 = 0;
    if (has1) {
        int r1 = t1 / SCOLS, c1 = t1 % SCOLS;
        int gy1 = min(y0 + r1, HH - 1);
        int gx1 = min(max(x0 - 1 + c1, 0), WW - 1);
        off1 = gy1 * WW + gx1;
    }

    // preload plane 0
    sb[0][tid] = grid[off0];
    if (has1) sb[0][t1] = grid[off1];
    __syncthreads();

    float a0 = 0.f, a1 = 0.f, a2 = 0.f, a3 = 0.f;
    int sidx = ty * SCOLS + tx + 1;

    for (int pi = 0; pi < NPLANES; pi++) {
        const float* cur = sb[pi & 1];

        // prefetch next plane into registers (hidden under compute)
        float n0 = 0.f, n1 = 0.f;
        if (pi < NPLANES - 1) {
            const float* pl = grid + (size_t)(pi + 1) * NN;
            n0 = pl[off0];
            if (has1) n1 = pl[off1];
        }

        float v  = cur[sidx];
        float e  = cur[sidx + 1];
        float sw = cur[sidx + SCOLS - 1];
        float s  = cur[sidx + SCOLS];
        float se = cur[sidx + SCOLS + 1];
        a0 += fabsf(v - e);
        a1 += fabsf(v - sw);
        a2 += fabsf(v - s);
        a3 += fabsf(v - se);

        if (pi < NPLANES - 1) {
            float* nxt = sb[(pi + 1) & 1];
            nxt[tid] = n0;
            if (has1) nxt[t1] = n1;
        }
        __syncthreads();
    }

    // ---- emit edges ----
    int x = x0 + tx, y = y0 + ty;
    int p = (y << 9) | x;
    const float inv = 1.0f / (float)NPLANES;
    const float SQ2 = 1.41421356237309515f;
    float f0 = a0 * inv, f1 = a1 * inv, f2 = a2 * inv, f3 = a3 * inv;

    int Sp = edge_start(y, x);
    // position of each forward dir within this node's valid-offset list
    int posE  = ((y > 0) & (x > 0)) + (y > 0) + ((y > 0) & (x < WW - 1)) + (x > 0);
    int posSW = posE + (x < WW - 1);
    int posS  = posSW + ((y < HH - 1) & (x > 0));
    int posSE = posS + (y < HH - 1);

    float* ei_dst = eio + E_CNT;
    float fp = (float)p;

    if (x < WW - 1) {  // E ; reverse = (0,-1) at (y, x+1)
        int q = p + 1;
        int er = edge_start(y, x + 1) + ((y > 0) ? (2 + (x < WW - 2)) : 0);
        int ef = Sp + posE;
        float2 a = make_float2(1.0f, f0);
        attr[ef] = a; attr[er] = a;
        eio[ef] = fp;        ei_dst[ef] = (float)q;
        eio[er] = (float)q;  ei_dst[er] = fp;
    }
    if (y < HH - 1 && x > 0) {  // SW ; reverse = (-1,1) at (y+1, x-1)
        int q = p + WW - 1;
        int er = edge_start(y + 1, x - 1) + 1 + (x > 1);
        int ef = Sp + posSW;
        float2 a = make_float2(SQ2, f1);
        attr[ef] = a; attr[er] = a;
        eio[ef] = fp;        ei_dst[ef] = (float)q;
        eio[er] = (float)q;  ei_dst[er] = fp;
    }
    if (y < HH - 1) {  // S ; reverse = (-1,0) at (y+1, x)
        int q = p + WW;
        int er = edge_start(y + 1, x) + (x > 0);
        int ef = Sp + posS;
        float2 a = make_float2(1.0f, f2);
        attr[ef] = a; attr[er] = a;
        eio[ef] = fp;        ei_dst[ef] = (float)q;
        eio[er] = (float)q;  ei_dst[er] = fp;
    }
    if (y < HH - 1 && x < WW - 1) {  // SE ; reverse = (-1,-1) at (y+1, x+1), pos 0
        int q = p + WW + 1;
        int er = edge_start(y + 1, x + 1);
        int ef = Sp + posSE;
        float2 a = make_float2(SQ2, f3);
        attr[ef] = a; attr[er] = a;
        eio[ef] = fp;        ei_dst[ef] = (float)q;
        eio[er] = (float)q;  ei_dst[er] = fp;
    }
}

// ---------------------------------------------------------------------------
// Output layout: node_features | edge_index(as float) | edge_attr
// edge_index input is no longer read at all — everything is analytic.
// ---------------------------------------------------------------------------
extern "C" void kernel_launch(void* const* d_in, const int* in_sizes, int n_in,
                              void* d_out, int out_size) {
    const float* grid = (const float*)d_in[0];

    float* out  = (float*)d_out;
    float* nf   = out;                               // B*N*C
    float* eio  = out + (size_t)BB * NN * CC;        // 2*E
    float2* attr = (float2*)(eio + 2 * E_CNT);       // E float2s

    transpose_kernel<<<dim3(NN / (256 * 4), BB), 256>>>(grid, nf);
    edge_fused_kernel<<<dim3(WW / TX, HH / TY), dim3(TX, TY)>>>(grid, eio, attr);
}

// round 4
// speedup vs baseline: 1.7314x; 1.4851x over previous
#include <cuda_runtime.h>
#include <cstddef>

// Fixed shapes: B=4, C=16, H=W=512
#define BB 4
#define CC 16
#define HH 512
#define WW 512
#define NN (HH * WW)
#define NPLANES (BB * CC)       // 64
#define E_CNT 2091012

// Edge-kernel tile
#define TX 32
#define TY 8
#define NT (TX * TY)            // 256 threads
#define SROWS (TY + 1)          // bottom halo
#define SCOLS (TX + 2)          // left+right halo
#define SELEMS (SROWS * SCOLS)  // 9*34 = 306
#define PF 4                    // planes per iteration
#define NITER (NPLANES / PF)    // 16

// Transpose smem pitch: 258 => ch*258 ≡ ch*2 (mod 32) => banks {0,8,16,24}+px : conflict-free
#define TP 258

// ---------------------------------------------------------------------------
// edge_start: analytic offset of node (h,w)'s first edge in reference order.
// ---------------------------------------------------------------------------
__device__ __forceinline__ int edge_start(int h, int w) {
    int R  = (h == 0) ? 0 : 2556 + (h - 1) * 4090;
    int vh = (h == 0 || h == HH - 1) ? 2 : 3;
    int Sv = (w == 0) ? 0 : 3 * w - 1;
    return R + vh * Sv - w;
}

// ---------------------------------------------------------------------------
// Kernel 1: NCHW -> (B*H*W, C) via smem staging. Coalesced loads AND stores.
// Block = 256 consecutive pixels of one batch image.
// ---------------------------------------------------------------------------
__global__ void __launch_bounds__(256) transpose_kernel(const float* __restrict__ in,
                                                        float* __restrict__ out) {
    __shared__ float s[CC * TP];

    int t  = threadIdx.x;
    int p0 = blockIdx.x * 256;
    int b  = blockIdx.y;

    const float* src = in + (size_t)b * CC * NN + p0 + t;
#pragma unroll
    for (int c = 0; c < CC; c++)
        s[c * TP + t] = src[(size_t)c * NN];
    __syncthreads();

    // write 4096 contiguous floats as 4 passes of 256 float4s
    float4* o = (float4*)(out + ((size_t)b * NN + p0) * CC);
    int ch = (t & 3) * 4;              // channel quad this thread emits
#pragma unroll
    for (int i = 0; i < 4; i++) {
        int px = i * 64 + (t >> 2);    // pixel within block tile
        float4 w = make_float4(s[(ch + 0) * TP + px],
                               s[(ch + 1) * TP + px],
                               s[(ch + 2) * TP + px],
                               s[(ch + 3) * TP + px]);
        o[i * 256 + t] = w;
    }
}

// ---------------------------------------------------------------------------
// Kernel 2: fused analytic edge_index + edge_attr. 32x8 tile, 4 planes per
// iteration (8 prefetch LDGs in flight), double-buffered smem.
// ---------------------------------------------------------------------------
__global__ void __launch_bounds__(NT) edge_fused_kernel(const float* __restrict__ grid,
                                                        float* __restrict__ eio,
                                                        float2* __restrict__ attr) {
    __shared__ float sb[2][PF][SELEMS];

    int tx = threadIdx.x, ty = threadIdx.y;
    int tid = ty * TX + tx;
    int x0 = blockIdx.x * TX, y0 = blockIdx.y * TY;

    // gmem offsets for this thread's (up to 2) smem slots, plane-independent
    int r0 = tid / SCOLS, c0 = tid % SCOLS;
    int off0 = min(y0 + r0, HH - 1) * WW + min(max(x0 - 1 + c0, 0), WW - 1);

    int t1 = tid + NT;
    bool has1 = t1 < SELEMS;
    int off1 = 0;
    if (has1) {
        int r1 = t1 / SCOLS, c1 = t1 % SCOLS;
        off1 = min(y0 + r1, HH - 1) * WW + min(max(x0 - 1 + c1, 0), WW - 1);
    }

    // preload plane group 0
#pragma unroll
    for (int j = 0; j < PF; j++) {
        const float* pl = grid + (size_t)j * NN;
        sb[0][j][tid] = pl[off0];
        if (has1) sb[0][j][t1] = pl[off1];
    }
    __syncthreads();

    float a0 = 0.f, a1 = 0.f, a2 = 0.f, a3 = 0.f;
    int sidx = ty * SCOLS + tx + 1;

    for (int g = 0; g < NITER; g++) {
        int buf = g & 1;

        // prefetch next group into registers (8 independent LDGs)
        float n0[PF], n1[PF];
        if (g < NITER - 1) {
            const float* pl = grid + (size_t)(g + 1) * PF * NN;
#pragma unroll
            for (int j = 0; j < PF; j++) {
                n0[j] = pl[(size_t)j * NN + off0];
                if (has1) n1[j] = pl[(size_t)j * NN + off1];
            }
        }

#pragma unroll
        for (int j = 0; j < PF; j++) {
            const float* cur = sb[buf][j];
            float v  = cur[sidx];
            float e  = cur[sidx + 1];
            float sw = cur[sidx + SCOLS - 1];
            float s  = cur[sidx + SCOLS];
            float se = cur[sidx + SCOLS + 1];
            a0 += fabsf(v - e);
            a1 += fabsf(v - sw);
            a2 += fabsf(v - s);
            a3 += fabsf(v - se);
        }

        if (g < NITER - 1) {
            __syncthreads();   // ensure everyone done reading buf^1 from 2 iters ago? (buf reuse)
#pragma unroll
            for (int j = 0; j < PF; j++) {
                sb[buf ^ 1][j][tid] = n0[j];
                if (has1) sb[buf ^ 1][j][t1] = n1[j];
            }
            __syncthreads();
        }
    }

    // ---- emit edges (both directions of each undirected pair) ----
    int x = x0 + tx, y = y0 + ty;
    int p = (y << 9) | x;
    const float inv = 1.0f / (float)NPLANES;
    const float SQ2 = 1.41421356237309515f;
    float f0 = a0 * inv, f1 = a1 * inv, f2 = a2 * inv, f3 = a3 * inv;

    int Sp = edge_start(y, x);
    int posE  = ((y > 0) & (x > 0)) + (y > 0) + ((y > 0) & (x < WW - 1)) + (x > 0);
    int posSW = posE + (x < WW - 1);
    int posS  = posSW + ((y < HH - 1) & (x > 0));
    int posSE = posS + (y < HH - 1);

    float* ei_dst = eio + E_CNT;
    float fp = (float)p;

    if (x < WW - 1) {  // E ; reverse (0,-1) at (y, x+1)
        int q = p + 1;
        int er = edge_start(y, x + 1) + ((y > 0) ? (2 + (x < WW - 2)) : 0);
        int ef = Sp + posE;
        float2 a = make_float2(1.0f, f0);
        attr[ef] = a; attr[er] = a;
        eio[ef] = fp;        ei_dst[ef] = (float)q;
        eio[er] = (float)q;  ei_dst[er] = fp;
    }
    if (y < HH - 1 && x > 0) {  // SW ; reverse (-1,1) at (y+1, x-1)
        int q = p + WW - 1;
        int er = edge_start(y + 1, x - 1) + 1 + (x > 1);
        int ef = Sp + posSW;
        float2 a = make_float2(SQ2, f1);
        attr[ef] = a; attr[er] = a;
        eio[ef] = fp;        ei_dst[ef] = (float)q;
        eio[er] = (float)q;  ei_dst[er] = fp;
    }
    if (y < HH - 1) {  // S ; reverse (-1,0) at (y+1, x)
        int q = p + WW;
        int er = edge_start(y + 1, x) + (x > 0);
        int ef = Sp + posS;
        float2 a = make_float2(1.0f, f2);
        attr[ef] = a; attr[er] = a;
        eio[ef] = fp;        ei_dst[ef] = (float)q;
        eio[er] = (float)q;  ei_dst[er] = fp;
    }
    if (y < HH - 1 && x < WW - 1) {  // SE ; reverse (-1,-1) at (y+1, x+1)
        int q = p + WW + 1;
        int er = edge_start(y + 1, x + 1);
        int ef = Sp + posSE;
        float2 a = make_float2(SQ2, f3);
        attr[ef] = a; attr[er] = a;
        eio[ef] = fp;        ei_dst[ef] = (float)q;
        eio[er] = (float)q;  ei_dst[er] = fp;
    }
}

// ---------------------------------------------------------------------------
extern "C" void kernel_launch(void* const* d_in, const int* in_sizes, int n_in,
                              void* d_out, int out_size) {
    const float* grid = (const float*)d_in[0];

    float* out   = (float*)d_out;
    float* nf    = out;
    float* eio   = out + (size_t)BB * NN * CC;
    float2* attr = (float2*)(eio + 2 * E_CNT);

    transpose_kernel<<<dim3(NN / 256, BB), 256>>>(grid, nf);
    edge_fused_kernel<<<dim3(WW / TX, HH / TY), dim3(TX, TY)>>>(grid, eio, attr);
}